// round 11
// baseline (speedup 1.0000x reference)
#include <cuda_runtime.h>
#include <cuda_bf16.h>

#define N_NODES   100000
#define N_EDGES   3200000
#define E_TOT     (N_EDGES + N_NODES)   // self loops appended
#define IN_DIM    512
#define HEADS     4
#define C1        8
#define C2        4
#define HC1       (HEADS*C1)   // 32
#define HC2       (HEADS*C2)   // 16
#define N_GRAPHS  64
#define OUT_DIM   10

#define SCAN_BS   1024
#define N_SCAN_BLOCKS ((N_NODES + SCAN_BS - 1) / SCAN_BS)   // 98

// ---------------- device scratch ----------------
__device__ __align__(16) float g_h1 [(size_t)N_NODES * HC1];
__device__ __align__(16) float g_es1[(size_t)N_NODES * HEADS];
__device__ __align__(16) float g_ed1[(size_t)N_NODES * HEADS];

__device__ __align__(16) float g_h2 [(size_t)N_NODES * HC2];
__device__ __align__(16) float g_es2[(size_t)N_NODES * HEADS];
__device__ __align__(16) float g_ed2[(size_t)N_NODES * HEADS];

__device__ __align__(16) float g_pool[N_GRAPHS * HC2];
__device__ float g_cnt [N_GRAPHS];

__device__ int g_deg[N_NODES];
__device__ int g_off[N_NODES + 1];
__device__ int g_pos[N_NODES];
__device__ int g_csr[E_TOT];
__device__ int g_blocksum[N_SCAN_BLOCKS];
__device__ int g_blockoff[N_SCAN_BLOCKS];

__device__ int g_is64;

// ---------------- generic helpers ----------------
__device__ __forceinline__ float lrelu(float v) { return v >= 0.f ? v : 0.2f * v; }

__device__ __forceinline__ void red4(float* p, float a, float b, float c, float d) {
    asm volatile("red.global.add.v4.f32 [%0], {%1,%2,%3,%4};"
                 :: "l"(p), "f"(a), "f"(b), "f"(c), "f"(d) : "memory");
}

__device__ __forceinline__ void load_edge(const void* ei, int i, int is64, int& s, int& d) {
    if (i < N_EDGES) {
        if (is64) {
            const long long* p = (const long long*)ei;
            s = (int)p[i];
            d = (int)p[(size_t)N_EDGES + i];
        } else {
            const int* p = (const int*)ei;
            s = p[i];
            d = p[(size_t)N_EDGES + i];
        }
    } else {
        s = d = i - N_EDGES;
    }
}

#define SW128(off) ((off) ^ (((off) >> 3) & 0x70))

__device__ __forceinline__ void cvt_split(float v, unsigned short& h, unsigned short& l) {
    __nv_bfloat16 hb = __float2bfloat16_rn(v);
    float r = v - __bfloat162float(hb);
    __nv_bfloat16 lb = __float2bfloat16_rn(r);
    h = __bfloat16_as_ushort(hb);
    l = __bfloat16_as_ushort(lb);
}

__device__ __forceinline__ void mma16816(float d[4], unsigned a0, unsigned a1,
                                         unsigned a2, unsigned a3,
                                         unsigned b0, unsigned b1) {
    asm volatile(
        "mma.sync.aligned.m16n8k16.row.col.f32.bf16.bf16.f32 "
        "{%0,%1,%2,%3}, {%4,%5,%6,%7}, {%8,%9}, {%0,%1,%2,%3};"
        : "+f"(d[0]), "+f"(d[1]), "+f"(d[2]), "+f"(d[3])
        : "r"(a0), "r"(a1), "r"(a2), "r"(a3), "r"(b0), "r"(b1));
}

// ---------------- detect (parallel) + init ----------------
__global__ void detect_kernel(const void* ei) {
    const unsigned long long* p = (const unsigned long long*)ei;
    int big = (p[threadIdx.x] >= (unsigned long long)N_NODES) ? 1 : 0;
    unsigned any_big = __ballot_sync(0xffffffffu, big);
    __shared__ unsigned sb[8];
    if ((threadIdx.x & 31) == 0) sb[threadIdx.x >> 5] = any_big;
    __syncthreads();
    if (threadIdx.x == 0) {
        unsigned m = 0;
        #pragma unroll
        for (int i = 0; i < 8; i++) m |= sb[i];
        g_is64 = (m == 0) ? 1 : 0;
    }
}

__global__ void init_kernel() {
    int t = blockIdx.x * blockDim.x + threadIdx.x;
    if (t < N_NODES) g_deg[t] = 0;
    if (t < N_GRAPHS * HC2) g_pool[t] = 0.f;
    if (t < N_GRAPHS)       g_cnt[t]  = 0.f;
}

// ---------------- CSR build ----------------
__global__ void count_kernel(const void* __restrict__ ei) {
    int i = blockIdx.x * blockDim.x + threadIdx.x;
    if (i >= E_TOT) return;
    int d;
    if (i < N_EDGES) {
        if (g_is64) d = (int)((const long long*)ei)[(size_t)N_EDGES + i];
        else        d = ((const int*)ei)[(size_t)N_EDGES + i];
    } else {
        d = i - N_EDGES;
    }
    atomicAdd(&g_deg[d], 1);
}

__global__ void scan1_kernel() {
    __shared__ int sm[SCAN_BS];
    const int t = threadIdx.x;
    const int idx = blockIdx.x * SCAN_BS + t;
    int v = (idx < N_NODES) ? g_deg[idx] : 0;
    sm[t] = v;
    __syncthreads();
    #pragma unroll
    for (int off = 1; off < SCAN_BS; off <<= 1) {
        int u = (t >= off) ? sm[t - off] : 0;
        __syncthreads();
        sm[t] += u;
        __syncthreads();
    }
    if (idx < N_NODES) g_off[idx] = sm[t] - v;
    if (t == SCAN_BS - 1) g_blocksum[blockIdx.x] = sm[t];
}

__global__ void scan2_kernel() {
    __shared__ int sm[128];
    const int t = threadIdx.x;
    int v = (t < N_SCAN_BLOCKS) ? g_blocksum[t] : 0;
    sm[t] = v;
    __syncthreads();
    #pragma unroll
    for (int off = 1; off < 128; off <<= 1) {
        int u = (t >= off) ? sm[t - off] : 0;
        __syncthreads();
        sm[t] += u;
        __syncthreads();
    }
    if (t < N_SCAN_BLOCKS) g_blockoff[t] = sm[t] - v;
}

__global__ void scan3_kernel() {
    const int idx = blockIdx.x * blockDim.x + threadIdx.x;
    if (idx < N_NODES) {
        int o = g_off[idx] + g_blockoff[blockIdx.x];
        g_off[idx] = o;
        g_pos[idx] = o;
    }
    if (idx == 0) g_off[N_NODES] = E_TOT;
}

__global__ void scatter_kernel(const void* __restrict__ ei) {
    int i = blockIdx.x * blockDim.x + threadIdx.x;
    if (i >= E_TOT) return;
    int s, d;
    load_edge(ei, i, g_is64, s, d);
    int p = atomicAdd(&g_pos[d], 1);
    g_csr[p] = s;
}

// ---------------- gemm1 (HMMA): h1 = x @ W1 via bf16 3-term split -------------
// CTA: 128 threads / 4 warps; tile 64 nodes x 32 cols; K in 8 chunks of 64.
// x, W1^T staged as SW128-swizzled bf16 hi/lo planes; each warp: 16 rows,
// 4 col-groups x 3 terms mma.m16n8k16 per K-step of 16.
#define GM_BN 64
#define GM_KC 64
__global__ __launch_bounds__(128) void gemm1_mma(const float* __restrict__ x,
                                                 const float* __restrict__ W1,
                                                 const float* __restrict__ a_src,
                                                 const float* __restrict__ a_dst) {
    __shared__ __align__(128) __nv_bfloat16 sAh[GM_BN * GM_KC];   // 8 KB
    __shared__ __align__(128) __nv_bfloat16 sAl[GM_BN * GM_KC];   // 8 KB
    __shared__ __align__(128) __nv_bfloat16 sBh[32 * GM_KC];      // 4 KB
    __shared__ __align__(128) __nv_bfloat16 sBl[32 * GM_KC];      // 4 KB
    __shared__ float sD[GM_BN * 33];                              // 8.25 KB
    __shared__ float sAs[HC1], sAd[HC1];

    const int tid  = threadIdx.x;
    const int wid  = tid >> 5;
    const int lane = tid & 31;
    const int nbase = blockIdx.x * GM_BN;

    if (tid < HC1) { sAs[tid] = a_src[tid]; sAd[tid] = a_dst[tid]; }

    float d[4][4];
    #pragma unroll
    for (int cg = 0; cg < 4; cg++)
        #pragma unroll
        for (int q = 0; q < 4; q++) d[cg][q] = 0.f;

    const int rg = lane >> 2;           // row/col group 0..7
    const int lo = lane & 3;            // lane offset 0..3
    const int r0 = wid * 16 + rg;       // fragment row 0 (tile-local)
    const int r1 = r0 + 8;

    for (int chunk = 0; chunk < 8; chunk++) {
        const int k0 = chunk * GM_KC;
        __syncthreads();
        // stage A: 64 rows x 64 k (16 float4 per row)
        for (int i = tid; i < GM_BN * (GM_KC / 4); i += 128) {
            const int row = i >> 4, kv = i & 15;
            float4 v = make_float4(0, 0, 0, 0);
            if (nbase + row < N_NODES)
                v = *(const float4*)(x + (size_t)(nbase + row) * IN_DIM + k0 + kv * 4);
            unsigned short h0, h1, h2, h3, l0, l1, l2, l3;
            cvt_split(v.x, h0, l0); cvt_split(v.y, h1, l1);
            cvt_split(v.z, h2, l2); cvt_split(v.w, h3, l3);
            const unsigned off = SW128((unsigned)(row * 128 + kv * 8));
            *(uint2*)((char*)sAh + off) = make_uint2((unsigned)h0 | ((unsigned)h1 << 16),
                                                     (unsigned)h2 | ((unsigned)h3 << 16));
            *(uint2*)((char*)sAl + off) = make_uint2((unsigned)l0 | ((unsigned)l1 << 16),
                                                     (unsigned)l2 | ((unsigned)l3 << 16));
        }
        // stage B: W1 chunk [64 k x 32 c] -> [c][k] K-major rows of 64 bf16
        for (int i = tid; i < GM_KC * 32; i += 128) {
            const int k = i >> 5, c = i & 31;
            unsigned short h, l;
            cvt_split(W1[(size_t)(k0 + k) * HC1 + c], h, l);
            const unsigned off = SW128((unsigned)(c * 128 + k * 2));
            *(__nv_bfloat16*)((char*)sBh + off) = __ushort_as_bfloat16(h);
            *(__nv_bfloat16*)((char*)sBl + off) = __ushort_as_bfloat16(l);
        }
        __syncthreads();

        #pragma unroll
        for (int ks = 0; ks < 4; ks++) {
            const unsigned cb0 = (unsigned)(ks * 32 + lo * 4);
            const unsigned cb1 = cb0 + 16;
            const unsigned ah0 = *(const unsigned*)((char*)sAh + SW128(r0 * 128 + cb0));
            const unsigned ah1 = *(const unsigned*)((char*)sAh + SW128(r1 * 128 + cb0));
            const unsigned ah2 = *(const unsigned*)((char*)sAh + SW128(r0 * 128 + cb1));
            const unsigned ah3 = *(const unsigned*)((char*)sAh + SW128(r1 * 128 + cb1));
            const unsigned al0 = *(const unsigned*)((char*)sAl + SW128(r0 * 128 + cb0));
            const unsigned al1 = *(const unsigned*)((char*)sAl + SW128(r1 * 128 + cb0));
            const unsigned al2 = *(const unsigned*)((char*)sAl + SW128(r0 * 128 + cb1));
            const unsigned al3 = *(const unsigned*)((char*)sAl + SW128(r1 * 128 + cb1));
            #pragma unroll
            for (int cg = 0; cg < 4; cg++) {
                const int n = cg * 8 + rg;
                const unsigned bh0 = *(const unsigned*)((char*)sBh + SW128(n * 128 + cb0));
                const unsigned bh1 = *(const unsigned*)((char*)sBh + SW128(n * 128 + cb1));
                const unsigned bl0 = *(const unsigned*)((char*)sBl + SW128(n * 128 + cb0));
                const unsigned bl1 = *(const unsigned*)((char*)sBl + SW128(n * 128 + cb1));
                mma16816(d[cg], ah0, ah1, ah2, ah3, bh0, bh1);
                mma16816(d[cg], ah0, ah1, ah2, ah3, bl0, bl1);
                mma16816(d[cg], al0, al1, al2, al3, bh0, bh1);
            }
        }
    }

    // D fragments -> smem -> coalesced epilogue
    __syncthreads();
    #pragma unroll
    for (int cg = 0; cg < 4; cg++) {
        const int c = cg * 8 + lo * 2;
        sD[r0 * 33 + c]     = d[cg][0];
        sD[r0 * 33 + c + 1] = d[cg][1];
        sD[r1 * 33 + c]     = d[cg][2];
        sD[r1 * 33 + c + 1] = d[cg][3];
    }
    __syncthreads();

    if (tid < GM_BN) {
        const int n = nbase + tid;
        if (n < N_NODES) {
            float h[HC1];
            #pragma unroll
            for (int c = 0; c < HC1; c++) h[c] = sD[tid * 33 + c];
            #pragma unroll
            for (int q = 0; q < 8; q++)
                *(float4*)&g_h1[(size_t)n * HC1 + q * 4] =
                    make_float4(h[4*q], h[4*q+1], h[4*q+2], h[4*q+3]);
            #pragma unroll
            for (int hh = 0; hh < HEADS; hh++) {
                float vs = 0.f, vd = 0.f;
                #pragma unroll
                for (int c = 0; c < C1; c++) {
                    vs += h[hh*C1 + c] * sAs[hh*C1 + c];
                    vd += h[hh*C1 + c] * sAd[hh*C1 + c];
                }
                g_es1[(size_t)n * HEADS + hh] = vs;
                g_ed1[(size_t)n * HEADS + hh] = vd;
            }
        }
    }
}

// ---------------- agg1: full-lane aggregation + fused gemm2 + scores2 --------
__global__ __launch_bounds__(256) void agg1_kernel(const float* __restrict__ b1,
                                                   const float* __restrict__ W2,
                                                   const float* __restrict__ a_src2,
                                                   const float* __restrict__ a_dst2) {
    __shared__ float sW2[HC1 * HC2];
    __shared__ __align__(16) float sB1[HC1];
    __shared__ float sA2s[HC2], sA2d[HC2];
    {
        const int t = threadIdx.x;
        for (int i = t; i < HC1 * HC2; i += 256) sW2[i] = W2[i];
        if (t < HC1) sB1[t] = b1[t];
        if (t < HC2) { sA2s[t] = a_src2[t]; sA2d[t] = a_dst2[t]; }
        __syncthreads();
    }

    const int warp = (blockIdx.x * blockDim.x + threadIdx.x) >> 5;
    if (warp >= N_NODES) return;
    const int lane = threadIdx.x & 31;
    const int d    = warp;
    const int beg  = g_off[d];
    const int end  = g_off[d + 1];
    const int le = lane >> 2, lh = lane & 3;
    const int e  = lane >> 3, p = lane & 7;
    const int hp = p >> 1;

    const float edv_s = g_ed1[(size_t)d * 4 + lh];

    float  den_l = 0.f;
    float4 acc = make_float4(0,0,0,0);

    for (int base = beg; base < end; base += 8) {
        const int idx = base + le;
        int s_e = -1; float w = 0.f;
        if (idx < end) {
            s_e = g_csr[idx];
            float es_s = g_es1[(size_t)s_e * 4 + lh];
            w = __expf(lrelu(es_s + edv_s));
            den_l += w;
        }
        #pragma unroll
        for (int j = 0; j < 2; j++) {
            const int he = e + j * 4;
            const int s_h = __shfl_sync(0xffffffffu, s_e, he * 4);
            const float w_h = __shfl_sync(0xffffffffu, w, he * 4 + hp);
            if (s_h >= 0) {
                float4 hv = *(const float4*)(g_h1 + (size_t)s_h * HC1 + p * 4);
                acc.x += w_h * hv.x; acc.y += w_h * hv.y;
                acc.z += w_h * hv.z; acc.w += w_h * hv.w;
            }
        }
    }

    #pragma unroll
    for (int o = 8; o <= 16; o <<= 1) {
        acc.x += __shfl_xor_sync(0xffffffffu, acc.x, o);
        acc.y += __shfl_xor_sync(0xffffffffu, acc.y, o);
        acc.z += __shfl_xor_sync(0xffffffffu, acc.z, o);
        acc.w += __shfl_xor_sync(0xffffffffu, acc.w, o);
    }
    #pragma unroll
    for (int o = 4; o <= 16; o <<= 1)
        den_l += __shfl_xor_sync(0xffffffffu, den_l, o);
    const float den_h = __shfl_sync(0xffffffffu, den_l, hp);
    const float ih = 1.f / (den_h + 1e-16f);

    float4 bb = *(const float4*)&sB1[p * 4];
    float r0 = fmaxf(acc.x * ih + bb.x, 0.f);
    float r1 = fmaxf(acc.y * ih + bb.y, 0.f);
    float r2 = fmaxf(acc.z * ih + bb.z, 0.f);
    float r3 = fmaxf(acc.w * ih + bb.w, 0.f);

    const int k0 = p * 4, c0 = e * 4;
    float4 pc = make_float4(0,0,0,0);
    #pragma unroll
    for (int kk = 0; kk < 4; kk++) {
        float rv = kk == 0 ? r0 : kk == 1 ? r1 : kk == 2 ? r2 : r3;
        const float* wrow = &sW2[(k0 + kk) * HC2 + c0];
        pc.x += rv * wrow[0]; pc.y += rv * wrow[1];
        pc.z += rv * wrow[2]; pc.w += rv * wrow[3];
    }
    #pragma unroll
    for (int o = 1; o <= 4; o <<= 1) {
        pc.x += __shfl_xor_sync(0xffffffffu, pc.x, o);
        pc.y += __shfl_xor_sync(0xffffffffu, pc.y, o);
        pc.z += __shfl_xor_sync(0xffffffffu, pc.z, o);
        pc.w += __shfl_xor_sync(0xffffffffu, pc.w, o);
    }
    if (p == 0) {
        *(float4*)&g_h2[(size_t)d * HC2 + c0] = pc;
        float es = pc.x * sA2s[c0] + pc.y * sA2s[c0+1] + pc.z * sA2s[c0+2] + pc.w * sA2s[c0+3];
        float ed = pc.x * sA2d[c0] + pc.y * sA2d[c0+1] + pc.z * sA2d[c0+2] + pc.w * sA2d[c0+3];
        g_es2[(size_t)d * HEADS + e] = es;
        g_ed2[(size_t)d * HEADS + e] = ed;
    }
}

// ---------------- agg2: full-lane aggregation (no shfls in loop) + pool ------
__global__ __launch_bounds__(256) void agg2_kernel(const float* __restrict__ b2,
                                                   const void* __restrict__ batch) {
    __shared__ __align__(16) float sB2[HC2];
    if (threadIdx.x < HC2) sB2[threadIdx.x] = b2[threadIdx.x];
    __syncthreads();

    const int warp = (blockIdx.x * blockDim.x + threadIdx.x) >> 5;
    if (warp >= N_NODES) return;
    const int lane = threadIdx.x & 31;
    const int d    = warp;
    const int beg  = g_off[d];
    const int end  = g_off[d + 1];
    const int le = lane >> 2, lh = lane & 3;

    const float edv_s = g_ed2[(size_t)d * 4 + lh];

    float  den_l = 0.f;
    float4 acc = make_float4(0,0,0,0);

    for (int base = beg; base < end; base += 8) {
        const int idx = base + le;
        if (idx < end) {
            int s = g_csr[idx];
            float es_s = g_es2[(size_t)s * 4 + lh];
            float w = __expf(lrelu(es_s + edv_s));
            den_l += w;
            float4 hv = *(const float4*)(g_h2 + (size_t)s * HC2 + lh * 4);
            acc.x += w * hv.x; acc.y += w * hv.y;
            acc.z += w * hv.z; acc.w += w * hv.w;
        }
    }

    #pragma unroll
    for (int o = 4; o <= 16; o <<= 1) {
        den_l += __shfl_xor_sync(0xffffffffu, den_l, o);
        acc.x += __shfl_xor_sync(0xffffffffu, acc.x, o);
        acc.y += __shfl_xor_sync(0xffffffffu, acc.y, o);
        acc.z += __shfl_xor_sync(0xffffffffu, acc.z, o);
        acc.w += __shfl_xor_sync(0xffffffffu, acc.w, o);
    }

    if (lane < 4) {
        int g;
        if (g_is64) g = (int)((const long long*)batch)[d];
        else        g = ((const int*)batch)[d];
        const float ih = 1.f / (den_l + 1e-16f);
        float4 bb = *(const float4*)&sB2[lane * 4];
        float o0 = fmaxf(acc.x * ih + bb.x, 0.f);
        float o1 = fmaxf(acc.y * ih + bb.y, 0.f);
        float o2 = fmaxf(acc.z * ih + bb.z, 0.f);
        float o3 = fmaxf(acc.w * ih + bb.w, 0.f);
        red4(g_pool + g * HC2 + lane * 4, o0, o1, o2, o3);
        if (lane == 0) atomicAdd(&g_cnt[g], 1.f);
    }
}

// ---------------- final ----------------
__global__ void final_kernel(const float* __restrict__ Wf, const float* __restrict__ bf,
                             float* __restrict__ out) {
    const int t = threadIdx.x;
    if (t >= N_GRAPHS * OUT_DIM) return;
    const int g = t / OUT_DIM;
    const int o = t % OUT_DIM;
    const float c = fmaxf(g_cnt[g], 1.f);
    float acc = bf[o];
    #pragma unroll
    for (int j = 0; j < HC2; j++)
        acc += (g_pool[g * HC2 + j] / c) * Wf[j * OUT_DIM + o];
    out[t] = acc;
}

// ---------------- stream/event holder ----------------
struct StreamHolder {
    cudaStream_t s2 = nullptr;
    cudaEvent_t  ev0 = nullptr, ev1 = nullptr;
    bool ok = false;
    StreamHolder() {
        if (cudaStreamCreateWithFlags(&s2, cudaStreamNonBlocking) != cudaSuccess) return;
        if (cudaEventCreateWithFlags(&ev0, cudaEventDisableTiming) != cudaSuccess) return;
        if (cudaEventCreateWithFlags(&ev1, cudaEventDisableTiming) != cudaSuccess) return;
        ok = true;
    }
};
static StreamHolder g_sh;

// ---------------- launch ----------------
extern "C" void kernel_launch(void* const* d_in, const int* in_sizes, int n_in,
                              void* d_out, int out_size) {
    const float* x       = (const float*)d_in[0];
    const void*  eidx    = d_in[1];
    const void*  batch   = d_in[2];
    const float* W1      = (const float*)d_in[3];
    const float* asrc1   = (const float*)d_in[4];
    const float* adst1   = (const float*)d_in[5];
    const float* b1      = (const float*)d_in[6];
    const float* W2      = (const float*)d_in[7];
    const float* asrc2   = (const float*)d_in[8];
    const float* adst2   = (const float*)d_in[9];
    const float* b2      = (const float*)d_in[10];
    const float* Wf      = (const float*)d_in[11];
    const float* bf      = (const float*)d_in[12];
    float* out = (float*)d_out;

    const int TB = 256;
    const int edgeGrid = (E_TOT + TB - 1) / TB;
    const int nodeGrid = (N_NODES + TB - 1) / TB;
    const int aggGrid  = (N_NODES * 32 + TB - 1) / TB;
    const int mmaGrid  = (N_NODES + GM_BN - 1) / GM_BN;

    if (g_sh.ok) {
        cudaEventRecord(g_sh.ev0, 0);
        cudaStreamWaitEvent(g_sh.s2, g_sh.ev0, 0);

        detect_kernel<<<1, 256, 0, g_sh.s2>>>(eidx);
        init_kernel<<<nodeGrid, TB, 0, g_sh.s2>>>();
        count_kernel<<<edgeGrid, TB, 0, g_sh.s2>>>(eidx);
        scan1_kernel<<<N_SCAN_BLOCKS, SCAN_BS, 0, g_sh.s2>>>();
        scan2_kernel<<<1, 128, 0, g_sh.s2>>>();
        scan3_kernel<<<N_SCAN_BLOCKS, SCAN_BS, 0, g_sh.s2>>>();
        scatter_kernel<<<edgeGrid, TB, 0, g_sh.s2>>>(eidx);
        cudaEventRecord(g_sh.ev1, g_sh.s2);

        gemm1_mma<<<mmaGrid, 128>>>(x, W1, asrc1, adst1);

        cudaStreamWaitEvent(0, g_sh.ev1, 0);
    } else {
        detect_kernel<<<1, 256>>>(eidx);
        init_kernel<<<nodeGrid, TB>>>();
        count_kernel<<<edgeGrid, TB>>>(eidx);
        scan1_kernel<<<N_SCAN_BLOCKS, SCAN_BS>>>();
        scan2_kernel<<<1, 128>>>();
        scan3_kernel<<<N_SCAN_BLOCKS, SCAN_BS>>>();
        scatter_kernel<<<edgeGrid, TB>>>(eidx);
        gemm1_mma<<<mmaGrid, 128>>>(x, W1, asrc1, adst1);
    }

    agg1_kernel<<<aggGrid, TB>>>(b1, W2, asrc2, adst2);
    agg2_kernel<<<aggGrid, TB>>>(b2, batch);
    final_kernel<<<1, N_GRAPHS * OUT_DIM>>>(Wf, bf, out);
}

// round 12
// speedup vs baseline: 1.2293x; 1.2293x over previous
#include <cuda_runtime.h>
#include <cuda_bf16.h>

#define N_NODES   100000
#define N_EDGES   3200000
#define E_TOT     (N_EDGES + N_NODES)   // self loops appended
#define IN_DIM    512
#define HEADS     4
#define C1        8
#define C2        4
#define HC1       (HEADS*C1)   // 32
#define HC2       (HEADS*C2)   // 16
#define N_GRAPHS  64
#define OUT_DIM   10

#define SCAN_BS   1024
#define N_SCAN_BLOCKS ((N_NODES + SCAN_BS - 1) / SCAN_BS)   // 98

// ---------------- device scratch ----------------
// h1/h2 stored as packed bf16x2 (uint) rows: h1 row = 16 uints (64B), h2 row = 8 uints (32B)
__device__ __align__(16) unsigned g_h1b[(size_t)N_NODES * (HC1 / 2)];
__device__ __align__(16) float g_es1[(size_t)N_NODES * HEADS];
__device__ __align__(16) float g_ed1[(size_t)N_NODES * HEADS];

__device__ __align__(16) unsigned g_h2b[(size_t)N_NODES * (HC2 / 2)];
__device__ __align__(16) float g_es2[(size_t)N_NODES * HEADS];
__device__ __align__(16) float g_ed2[(size_t)N_NODES * HEADS];

__device__ __align__(16) float g_pool[N_GRAPHS * HC2];
__device__ float g_cnt [N_GRAPHS];

__device__ int g_deg[N_NODES];
__device__ int g_off[N_NODES + 1];
__device__ int g_pos[N_NODES];
__device__ int g_csr[E_TOT];
__device__ int g_blocksum[N_SCAN_BLOCKS];
__device__ int g_blockoff[N_SCAN_BLOCKS];

__device__ int g_is64;

// ---------------- helpers ----------------
__device__ __forceinline__ float lrelu(float v) { return v >= 0.f ? v : 0.2f * v; }

__device__ __forceinline__ void red4(float* p, float a, float b, float c, float d) {
    asm volatile("red.global.add.v4.f32 [%0], {%1,%2,%3,%4};"
                 :: "l"(p), "f"(a), "f"(b), "f"(c), "f"(d) : "memory");
}

__device__ __forceinline__ unsigned pack_bf2(float a, float b) {
    __nv_bfloat162 t = __floats2bfloat162_rn(a, b);
    return *(unsigned*)&t;
}
__device__ __forceinline__ float2 upk_bf2(unsigned u) {
    return __bfloat1622float2(*(__nv_bfloat162*)&u);
}

__device__ __forceinline__ void load_edge(const void* ei, int i, int is64, int& s, int& d) {
    if (i < N_EDGES) {
        if (is64) {
            const long long* p = (const long long*)ei;
            s = (int)p[i];
            d = (int)p[(size_t)N_EDGES + i];
        } else {
            const int* p = (const int*)ei;
            s = p[i];
            d = p[(size_t)N_EDGES + i];
        }
    } else {
        s = d = i - N_EDGES;
    }
}

// ---------------- init (fused dtype detect) ----------------
__global__ void init_kernel(const void* ei) {
    int t = blockIdx.x * blockDim.x + threadIdx.x;
    if (t < N_NODES) g_deg[t] = 0;
    if (t < N_GRAPHS * HC2) g_pool[t] = 0.f;
    if (t < N_GRAPHS)       g_cnt[t]  = 0.f;
    if (blockIdx.x == 0) {
        const unsigned long long* p = (const unsigned long long*)ei;
        int big = (p[threadIdx.x] >= (unsigned long long)N_NODES) ? 1 : 0;
        unsigned any_big = __ballot_sync(0xffffffffu, big);
        __shared__ unsigned sb[8];
        if ((threadIdx.x & 31) == 0) sb[threadIdx.x >> 5] = any_big;
        __syncthreads();
        if (threadIdx.x == 0) {
            unsigned m = 0;
            #pragma unroll
            for (int i = 0; i < 8; i++) m |= sb[i];
            g_is64 = (m == 0) ? 1 : 0;
        }
    }
}

// ---------------- CSR build ----------------
__global__ void count_kernel(const void* __restrict__ ei) {
    int i = blockIdx.x * blockDim.x + threadIdx.x;
    if (i >= E_TOT) return;
    int d;
    if (i < N_EDGES) {
        if (g_is64) d = (int)((const long long*)ei)[(size_t)N_EDGES + i];
        else        d = ((const int*)ei)[(size_t)N_EDGES + i];
    } else {
        d = i - N_EDGES;
    }
    atomicAdd(&g_deg[d], 1);
}

__global__ void scan1_kernel() {
    __shared__ int sm[SCAN_BS];
    const int t = threadIdx.x;
    const int idx = blockIdx.x * SCAN_BS + t;
    int v = (idx < N_NODES) ? g_deg[idx] : 0;
    sm[t] = v;
    __syncthreads();
    #pragma unroll
    for (int off = 1; off < SCAN_BS; off <<= 1) {
        int u = (t >= off) ? sm[t - off] : 0;
        __syncthreads();
        sm[t] += u;
        __syncthreads();
    }
    if (idx < N_NODES) g_off[idx] = sm[t] - v;
    if (t == SCAN_BS - 1) g_blocksum[blockIdx.x] = sm[t];
}

__global__ void scan2_kernel() {
    __shared__ int sm[128];
    const int t = threadIdx.x;
    int v = (t < N_SCAN_BLOCKS) ? g_blocksum[t] : 0;
    sm[t] = v;
    __syncthreads();
    #pragma unroll
    for (int off = 1; off < 128; off <<= 1) {
        int u = (t >= off) ? sm[t - off] : 0;
        __syncthreads();
        sm[t] += u;
        __syncthreads();
    }
    if (t < N_SCAN_BLOCKS) g_blockoff[t] = sm[t] - v;
}

__global__ void scan3_kernel() {
    const int idx = blockIdx.x * blockDim.x + threadIdx.x;
    if (idx < N_NODES) {
        int o = g_off[idx] + g_blockoff[blockIdx.x];
        g_off[idx] = o;
        g_pos[idx] = o;
    }
    if (idx == 0) g_off[N_NODES] = E_TOT;
}

__global__ void scatter_kernel(const void* __restrict__ ei) {
    int i = blockIdx.x * blockDim.x + threadIdx.x;
    if (i >= E_TOT) return;
    int s, d;
    load_edge(ei, i, g_is64, s, d);
    int p = atomicAdd(&g_pos[d], 1);
    g_csr[p] = s;
}

// ---------------- gemm1: h1 = x @ W1 (512->32), 8x8 register tile ------------
// scalar FMA (proven R6/R9); epilogue stores h1 as packed bf16x2 + fp32 scores.
#define G1_BN 256
#define G1_BK 32
__global__ __launch_bounds__(128) void gemm1_kernel(const float* __restrict__ x,
                                                    const float* __restrict__ W1,
                                                    const float* __restrict__ a_src,
                                                    const float* __restrict__ a_dst) {
    __shared__ float sX[G1_BN][36];
    __shared__ float sW[G1_BK][36];
    const int tid = threadIdx.x;
    const int nbase = blockIdx.x * G1_BN;
    const int ng = tid >> 2;
    const int cg = tid & 3;
    const int c0 = cg * 8;

    float4 acc[8][2];
    #pragma unroll
    for (int j = 0; j < 8; j++) { acc[j][0] = make_float4(0,0,0,0); acc[j][1] = make_float4(0,0,0,0); }

    for (int k0 = 0; k0 < IN_DIM; k0 += G1_BK) {
        __syncthreads();
        for (int i = tid; i < G1_BN * (G1_BK / 4); i += 128) {
            int n = i >> 3, kv = i & 7;
            float4 v = make_float4(0,0,0,0);
            if (nbase + n < N_NODES)
                v = *(const float4*)(x + (size_t)(nbase + n) * IN_DIM + k0 + kv * 4);
            *(float4*)&sX[n][kv * 4] = v;
        }
        for (int i = tid; i < G1_BK * 32; i += 128) {
            int k = i >> 5, c = i & 31;
            sW[k][c] = W1[(size_t)(k0 + k) * 32 + c];
        }
        __syncthreads();
        #pragma unroll
        for (int k4 = 0; k4 < G1_BK; k4 += 4) {
            float4 xt[8];
            #pragma unroll
            for (int j = 0; j < 8; j++) xt[j] = *(const float4*)&sX[ng + j * 32][k4];
            #pragma unroll
            for (int kk = 0; kk < 4; kk++) {
                float4 w0 = *(const float4*)&sW[k4 + kk][c0];
                float4 w1 = *(const float4*)&sW[k4 + kk][c0 + 4];
                #pragma unroll
                for (int j = 0; j < 8; j++) {
                    float xv = (kk == 0) ? xt[j].x : (kk == 1) ? xt[j].y : (kk == 2) ? xt[j].z : xt[j].w;
                    acc[j][0].x += xv * w0.x; acc[j][0].y += xv * w0.y;
                    acc[j][0].z += xv * w0.z; acc[j][0].w += xv * w0.w;
                    acc[j][1].x += xv * w1.x; acc[j][1].y += xv * w1.y;
                    acc[j][1].z += xv * w1.z; acc[j][1].w += xv * w1.w;
                }
            }
        }
    }

    float as0 = a_src[c0+0], as1 = a_src[c0+1], as2 = a_src[c0+2], as3 = a_src[c0+3];
    float as4 = a_src[c0+4], as5 = a_src[c0+5], as6 = a_src[c0+6], as7 = a_src[c0+7];
    float ad0 = a_dst[c0+0], ad1 = a_dst[c0+1], ad2 = a_dst[c0+2], ad3 = a_dst[c0+3];
    float ad4 = a_dst[c0+4], ad5 = a_dst[c0+5], ad6 = a_dst[c0+6], ad7 = a_dst[c0+7];
    #pragma unroll
    for (int j = 0; j < 8; j++) {
        int n = nbase + ng + j * 32;
        if (n >= N_NODES) continue;
        // packed bf16 store: 8 floats -> 4 uints (16B)
        uint4 hb;
        hb.x = pack_bf2(acc[j][0].x, acc[j][0].y);
        hb.y = pack_bf2(acc[j][0].z, acc[j][0].w);
        hb.z = pack_bf2(acc[j][1].x, acc[j][1].y);
        hb.w = pack_bf2(acc[j][1].z, acc[j][1].w);
        *(uint4*)&g_h1b[(size_t)n * (HC1/2) + cg * 4] = hb;
        float es = acc[j][0].x*as0 + acc[j][0].y*as1 + acc[j][0].z*as2 + acc[j][0].w*as3
                 + acc[j][1].x*as4 + acc[j][1].y*as5 + acc[j][1].z*as6 + acc[j][1].w*as7;
        float ed = acc[j][0].x*ad0 + acc[j][0].y*ad1 + acc[j][0].z*ad2 + acc[j][0].w*ad3
                 + acc[j][1].x*ad4 + acc[j][1].y*ad5 + acc[j][1].z*ad6 + acc[j][1].w*ad7;
        g_es1[(size_t)n * HEADS + cg] = es;
        g_ed1[(size_t)n * HEADS + cg] = ed;
    }
}

// ---------------- agg1: full-lane aggregation (bf16 gathers) + fused gemm2 ---
__global__ __launch_bounds__(256) void agg1_kernel(const float* __restrict__ b1,
                                                   const float* __restrict__ W2,
                                                   const float* __restrict__ a_src2,
                                                   const float* __restrict__ a_dst2) {
    __shared__ float sW2[HC1 * HC2];
    __shared__ __align__(16) float sB1[HC1];
    __shared__ float sA2s[HC2], sA2d[HC2];
    {
        const int t = threadIdx.x;
        for (int i = t; i < HC1 * HC2; i += 256) sW2[i] = W2[i];
        if (t < HC1) sB1[t] = b1[t];
        if (t < HC2) { sA2s[t] = a_src2[t]; sA2d[t] = a_dst2[t]; }
        __syncthreads();
    }

    const int warp = (blockIdx.x * blockDim.x + threadIdx.x) >> 5;
    if (warp >= N_NODES) return;
    const int lane = threadIdx.x & 31;
    const int d    = warp;
    const int beg  = g_off[d];
    const int end  = g_off[d + 1];
    const int le = lane >> 2, lh = lane & 3;   // exp phase: edge slot, head
    const int e  = lane >> 3, p = lane & 7;    // gather phase: edge-in-half, part
    const int hp = p >> 1;                     // head of part p

    const float edv_s = g_ed1[(size_t)d * 4 + lh];

    float  den_l = 0.f;
    float4 acc = make_float4(0,0,0,0);

    for (int base = beg; base < end; base += 8) {
        const int idx = base + le;
        int s_e = -1; float w = 0.f;
        if (idx < end) {
            s_e = g_csr[idx];
            float es_s = g_es1[(size_t)s_e * 4 + lh];
            w = __expf(lrelu(es_s + edv_s));
            den_l += w;
        }
        #pragma unroll
        for (int j = 0; j < 2; j++) {
            const int he = e + j * 4;                            // edge slot 0..7
            const int s_h = __shfl_sync(0xffffffffu, s_e, he * 4);
            const float w_h = __shfl_sync(0xffffffffu, w, he * 4 + hp);
            if (s_h >= 0) {
                uint2 hv = *(const uint2*)(g_h1b + (size_t)s_h * (HC1/2) + p * 2);
                float2 f0 = upk_bf2(hv.x), f1 = upk_bf2(hv.y);
                acc.x += w_h * f0.x; acc.y += w_h * f0.y;
                acc.z += w_h * f1.x; acc.w += w_h * f1.y;
            }
        }
    }

    // acc: reduce over lanes with same p (xor 8, 16)
    #pragma unroll
    for (int o = 8; o <= 16; o <<= 1) {
        acc.x += __shfl_xor_sync(0xffffffffu, acc.x, o);
        acc.y += __shfl_xor_sync(0xffffffffu, acc.y, o);
        acc.z += __shfl_xor_sync(0xffffffffu, acc.z, o);
        acc.w += __shfl_xor_sync(0xffffffffu, acc.w, o);
    }
    // den: reduce over edge slots (xor 4, 8, 16) -> every lane holds den[its lh]
    #pragma unroll
    for (int o = 4; o <= 16; o <<= 1)
        den_l += __shfl_xor_sync(0xffffffffu, den_l, o);
    const float den_h = __shfl_sync(0xffffffffu, den_l, hp);
    const float ih = 1.f / (den_h + 1e-16f);

    float4 bb = *(const float4*)&sB1[p * 4];
    float r0 = fmaxf(acc.x * ih + bb.x, 0.f);
    float r1 = fmaxf(acc.y * ih + bb.y, 0.f);
    float r2 = fmaxf(acc.z * ih + bb.z, 0.f);
    float r3 = fmaxf(acc.w * ih + bb.w, 0.f);

    // fused gemm2: lane computes partials for h2 cols e*4..e*4+3 over k = p*4..p*4+3
    const int k0 = p * 4, c0 = e * 4;
    float4 pc = make_float4(0,0,0,0);
    #pragma unroll
    for (int kk = 0; kk < 4; kk++) {
        float rv = kk == 0 ? r0 : kk == 1 ? r1 : kk == 2 ? r2 : r3;
        const float* wrow = &sW2[(k0 + kk) * HC2 + c0];
        pc.x += rv * wrow[0]; pc.y += rv * wrow[1];
        pc.z += rv * wrow[2]; pc.w += rv * wrow[3];
    }
    #pragma unroll
    for (int o = 1; o <= 4; o <<= 1) {
        pc.x += __shfl_xor_sync(0xffffffffu, pc.x, o);
        pc.y += __shfl_xor_sync(0xffffffffu, pc.y, o);
        pc.z += __shfl_xor_sync(0xffffffffu, pc.z, o);
        pc.w += __shfl_xor_sync(0xffffffffu, pc.w, o);
    }
    if (p == 0) {
        *(uint2*)&g_h2b[(size_t)d * (HC2/2) + e * 2] =
            make_uint2(pack_bf2(pc.x, pc.y), pack_bf2(pc.z, pc.w));
        float es = pc.x * sA2s[c0] + pc.y * sA2s[c0+1] + pc.z * sA2s[c0+2] + pc.w * sA2s[c0+3];
        float ed = pc.x * sA2d[c0] + pc.y * sA2d[c0+1] + pc.z * sA2d[c0+2] + pc.w * sA2d[c0+3];
        g_es2[(size_t)d * HEADS + e] = es;
        g_ed2[(size_t)d * HEADS + e] = ed;
    }
}

// ---------------- agg2: full-lane aggregation (bf16 gathers) + relu+pool -----
__global__ __launch_bounds__(256) void agg2_kernel(const float* __restrict__ b2,
                                                   const void* __restrict__ batch) {
    __shared__ __align__(16) float sB2[HC2];
    if (threadIdx.x < HC2) sB2[threadIdx.x] = b2[threadIdx.x];
    __syncthreads();

    const int warp = (blockIdx.x * blockDim.x + threadIdx.x) >> 5;
    if (warp >= N_NODES) return;
    const int lane = threadIdx.x & 31;
    const int d    = warp;
    const int beg  = g_off[d];
    const int end  = g_off[d + 1];
    const int le = lane >> 2, lh = lane & 3;

    const float edv_s = g_ed2[(size_t)d * 4 + lh];

    float  den_l = 0.f;
    float4 acc = make_float4(0,0,0,0);

    for (int base = beg; base < end; base += 8) {
        const int idx = base + le;
        if (idx < end) {
            int s = g_csr[idx];
            float es_s = g_es2[(size_t)s * 4 + lh];
            float w = __expf(lrelu(es_s + edv_s));
            den_l += w;
            uint2 hv = *(const uint2*)(g_h2b + (size_t)s * (HC2/2) + lh * 2);
            float2 f0 = upk_bf2(hv.x), f1 = upk_bf2(hv.y);
            acc.x += w * f0.x; acc.y += w * f0.y;
            acc.z += w * f1.x; acc.w += w * f1.y;
        }
    }

    #pragma unroll
    for (int o = 4; o <= 16; o <<= 1) {
        den_l += __shfl_xor_sync(0xffffffffu, den_l, o);
        acc.x += __shfl_xor_sync(0xffffffffu, acc.x, o);
        acc.y += __shfl_xor_sync(0xffffffffu, acc.y, o);
        acc.z += __shfl_xor_sync(0xffffffffu, acc.z, o);
        acc.w += __shfl_xor_sync(0xffffffffu, acc.w, o);
    }

    if (lane < 4) {
        int g;
        if (g_is64) g = (int)((const long long*)batch)[d];
        else        g = ((const int*)batch)[d];
        const float ih = 1.f / (den_l + 1e-16f);
        float4 bb = *(const float4*)&sB2[lane * 4];
        float o0 = fmaxf(acc.x * ih + bb.x, 0.f);
        float o1 = fmaxf(acc.y * ih + bb.y, 0.f);
        float o2 = fmaxf(acc.z * ih + bb.z, 0.f);
        float o3 = fmaxf(acc.w * ih + bb.w, 0.f);
        red4(g_pool + g * HC2 + lane * 4, o0, o1, o2, o3);
        if (lane == 0) atomicAdd(&g_cnt[g], 1.f);
    }
}

// ---------------- final ----------------
__global__ void final_kernel(const float* __restrict__ Wf, const float* __restrict__ bf,
                             float* __restrict__ out) {
    const int t = threadIdx.x;
    if (t >= N_GRAPHS * OUT_DIM) return;
    const int g = t / OUT_DIM;
    const int o = t % OUT_DIM;
    const float c = fmaxf(g_cnt[g], 1.f);
    float acc = bf[o];
    #pragma unroll
    for (int j = 0; j < HC2; j++)
        acc += (g_pool[g * HC2 + j] / c) * Wf[j * OUT_DIM + o];
    out[t] = acc;
}

// ---------------- stream/event holder ----------------
struct StreamHolder {
    cudaStream_t s2 = nullptr;
    cudaEvent_t  ev0 = nullptr, ev1 = nullptr;
    bool ok = false;
    StreamHolder() {
        if (cudaStreamCreateWithFlags(&s2, cudaStreamNonBlocking) != cudaSuccess) return;
        if (cudaEventCreateWithFlags(&ev0, cudaEventDisableTiming) != cudaSuccess) return;
        if (cudaEventCreateWithFlags(&ev1, cudaEventDisableTiming) != cudaSuccess) return;
        ok = true;
    }
};
static StreamHolder g_sh;

// ---------------- launch ----------------
extern "C" void kernel_launch(void* const* d_in, const int* in_sizes, int n_in,
                              void* d_out, int out_size) {
    const float* x       = (const float*)d_in[0];
    const void*  eidx    = d_in[1];
    const void*  batch   = d_in[2];
    const float* W1      = (const float*)d_in[3];
    const float* asrc1   = (const float*)d_in[4];
    const float* adst1   = (const float*)d_in[5];
    const float* b1      = (const float*)d_in[6];
    const float* W2      = (const float*)d_in[7];
    const float* asrc2   = (const float*)d_in[8];
    const float* adst2   = (const float*)d_in[9];
    const float* b2      = (const float*)d_in[10];
    const float* Wf      = (const float*)d_in[11];
    const float* bf      = (const float*)d_in[12];
    float* out = (float*)d_out;

    const int TB = 256;
    const int edgeGrid = (E_TOT + TB - 1) / TB;
    const int nodeGrid = (N_NODES + TB - 1) / TB;
    const int aggGrid  = (N_NODES * 32 + TB - 1) / TB;

    if (g_sh.ok) {
        cudaEventRecord(g_sh.ev0, 0);
        cudaStreamWaitEvent(g_sh.s2, g_sh.ev0, 0);

        init_kernel<<<nodeGrid, TB, 0, g_sh.s2>>>(eidx);
        count_kernel<<<edgeGrid, TB, 0, g_sh.s2>>>(eidx);
        scan1_kernel<<<N_SCAN_BLOCKS, SCAN_BS, 0, g_sh.s2>>>();
        scan2_kernel<<<1, 128, 0, g_sh.s2>>>();
        scan3_kernel<<<N_SCAN_BLOCKS, SCAN_BS, 0, g_sh.s2>>>();
        scatter_kernel<<<edgeGrid, TB, 0, g_sh.s2>>>(eidx);
        cudaEventRecord(g_sh.ev1, g_sh.s2);

        gemm1_kernel<<<(N_NODES + G1_BN - 1) / G1_BN, 128>>>(x, W1, asrc1, adst1);

        cudaStreamWaitEvent(0, g_sh.ev1, 0);
    } else {
        init_kernel<<<nodeGrid, TB>>>(eidx);
        count_kernel<<<edgeGrid, TB>>>(eidx);
        scan1_kernel<<<N_SCAN_BLOCKS, SCAN_BS>>>();
        scan2_kernel<<<1, 128>>>();
        scan3_kernel<<<N_SCAN_BLOCKS, SCAN_BS>>>();
        scatter_kernel<<<edgeGrid, TB>>>(eidx);
        gemm1_kernel<<<(N_NODES + G1_BN - 1) / G1_BN, 128>>>(x, W1, asrc1, adst1);
    }

    agg1_kernel<<<aggGrid, TB>>>(b1, W2, asrc2, adst2);
    agg2_kernel<<<aggGrid, TB>>>(b2, batch);
    final_kernel<<<1, N_GRAPHS * OUT_DIM>>>(Wf, bf, out);
}